// round 8
// baseline (speedup 1.0000x reference)
#include <cuda_runtime.h>
#include <cuda_fp16.h>
#include <cstdint>

// Problem constants
#define BB 4
#define TT 32
#define NN 32
#define FF 16
#define GH 64
#define LSTM_IN 2048     // NN*GH
#define LSTM_H 4096
#define GATES 16384      // 4*LSTM_H
#define E_EDGES 256

// Scratch (device globals; no dynamic allocation allowed)
__device__ float g_A[NN * NN];
__device__ __align__(16) __half g_seq_h[BB * TT * LSTM_IN];       // 512 KB fp16
__device__ float g_xproj[TT * BB * GATES];                        // 8 MB
__device__ __align__(16) __half g_h16[2][BB * LSTM_H];            // fp16 hidden, dbl-buf
__device__ float g_c[BB * LSTM_H];
__device__ __align__(16) __half g_Whh_h[(size_t)GATES * LSTM_H];  // 128 MiB fp16
__device__ __align__(16) __half g_Wih_h[(size_t)GATES * LSTM_IN]; // 64 MiB fp16

__device__ __forceinline__ uint32_t smem_u32(const void* p) {
    return (uint32_t)__cvta_generic_to_shared(p);
}
#define CP_ASYNC16(dst_u32, src_ptr) \
    asm volatile("cp.async.cg.shared.global [%0], [%1], 16;" :: "r"(dst_u32), "l"(src_ptr))
#define CP_COMMIT() asm volatile("cp.async.commit_group;" ::: "memory")
#define SWZ(x) ((x) ^ (((x) >> 3) & 0x70))

// ---------- 1) adjacency build (handles int32 or int64 edge_index) ----------
__global__ void build_adj_kernel(const int* __restrict__ ei32) {
    __shared__ int is32flag;
    __shared__ int deg[NN];
    __shared__ float dinv[NN];
    __shared__ float As[NN * NN];
    int tid = threadIdx.x;
    if (tid == 0) is32flag = 0;
    for (int i = tid; i < NN; i += blockDim.x) deg[i] = 1;  // self loop
    for (int i = tid; i < NN * NN; i += blockDim.x) As[i] = 0.f;
    __syncthreads();
    int any = 0;
    for (int w = tid * 2 + 1; w < 512; w += blockDim.x * 2) any |= ei32[w];
    if (any) atomicOr(&is32flag, 1);
    __syncthreads();
    const int is32 = is32flag;
    for (int e = tid; e < E_EDGES; e += blockDim.x) {
        int dst = is32 ? ei32[E_EDGES + e] : ei32[2 * (E_EDGES + e)];
        atomicAdd(&deg[dst], 1);
    }
    __syncthreads();
    for (int i = tid; i < NN; i += blockDim.x) dinv[i] = rsqrtf((float)deg[i]);
    __syncthreads();
    for (int e = tid; e < E_EDGES; e += blockDim.x) {
        int src = is32 ? ei32[e] : ei32[2 * e];
        int dst = is32 ? ei32[E_EDGES + e] : ei32[2 * (E_EDGES + e)];
        atomicAdd(&As[dst * NN + src], dinv[src] * dinv[dst]);
    }
    for (int n = tid; n < NN; n += blockDim.x)
        atomicAdd(&As[n * NN + n], dinv[n] * dinv[n]);
    __syncthreads();
    for (int i = tid; i < NN * NN; i += blockDim.x) g_A[i] = As[i];
}

// ---------- 2) LayerNorm + GCN x2 -> seq (fp16) ----------
__global__ void __launch_bounds__(256) gcn_kernel(
    const float* __restrict__ x, const float* __restrict__ ln_g,
    const float* __restrict__ ln_b, const float* __restrict__ W1,
    const float* __restrict__ b1, const float* __restrict__ W2,
    const float* __restrict__ b2) {
    __shared__ float xln[NN * FF];
    __shared__ float bufA[NN * GH];
    __shared__ float bufB[NN * GH];
    __shared__ float As[NN * NN];
    int tid = threadIdx.x;
    int bt = blockIdx.x;  // b*TT + t
    const float* xp = x + (size_t)bt * NN * FF;

    for (int i = tid; i < NN * NN; i += 256) As[i] = g_A[i];
    if (tid < NN) {
        float v[FF];
        float mu = 0.f;
#pragma unroll
        for (int f = 0; f < FF; f++) { v[f] = xp[tid * FF + f]; mu += v[f]; }
        mu *= (1.f / FF);
        float var = 0.f;
#pragma unroll
        for (int f = 0; f < FF; f++) { float d = v[f] - mu; var += d * d; }
        var *= (1.f / FF);
        float r = rsqrtf(var + 1e-5f);
#pragma unroll
        for (int f = 0; f < FF; f++)
            xln[tid * FF + f] = (v[f] - mu) * r * ln_g[f] + ln_b[f];
    }
    __syncthreads();
    for (int o = tid; o < NN * GH; o += 256) {
        int n = o >> 6, g = o & 63;
        float s = 0.f;
#pragma unroll
        for (int f = 0; f < FF; f++) s += xln[n * FF + f] * W1[f * GH + g];
        bufA[o] = s;
    }
    __syncthreads();
    for (int o = tid; o < NN * GH; o += 256) {
        int n = o >> 6, g = o & 63;
        float s = b1[g];
#pragma unroll 8
        for (int sn = 0; sn < NN; sn++) s += As[n * NN + sn] * bufA[sn * GH + g];
        bufB[o] = s;
    }
    __syncthreads();
    for (int o = tid; o < NN * GH; o += 256) {
        int n = o >> 6, g = o & 63;
        float s = 0.f;
#pragma unroll 8
        for (int f = 0; f < GH; f++) s += bufB[n * GH + f] * W2[f * GH + g];
        bufA[o] = s;
    }
    __syncthreads();
    for (int o = tid; o < NN * GH; o += 256) {
        int n = o >> 6, g = o & 63;
        float s = b2[g];
#pragma unroll 8
        for (int sn = 0; sn < NN; sn++) s += As[n * NN + sn] * bufA[sn * GH + g];
        g_seq_h[(size_t)bt * LSTM_IN + o] = __float2half_rn(s);
    }
}

// ---------- 3) converts ----------
__global__ void __launch_bounds__(256) convert_whh_kernel(const float* __restrict__ Whh) {
    size_t i = ((size_t)blockIdx.x * 256 + threadIdx.x) * 4;
    float4 v = *(const float4*)(Whh + i);
    __half2* out = (__half2*)(g_Whh_h + i);
    out[0] = __floats2half2_rn(v.x, v.y);
    out[1] = __floats2half2_rn(v.z, v.w);
}
__global__ void __launch_bounds__(256) convert_wih_kernel(const float* __restrict__ Wih) {
    size_t i = ((size_t)blockIdx.x * 256 + threadIdx.x) * 4;
    float4 v = *(const float4*)(Wih + i);
    __half2* out = (__half2*)(g_Wih_h + i);
    out[0] = __floats2half2_rn(v.x, v.y);
    out[1] = __floats2half2_rn(v.z, v.w);
}

// ---------- 4) x_proj GEMM on tensor cores (HMMA) -----------------------------
__global__ void __launch_bounds__(256) xproj_hmma_kernel(
    const float* __restrict__ b_ih, const float* __restrict__ b_hh) {
    __shared__ __align__(16) char sm[49152];  // A: 2x16KB @0, B: 2x8KB @32768
    const uint32_t smA = smem_u32(sm);
    const uint32_t smB = smA + 32768;
    int tid = threadIdx.x, wid = tid >> 5, lane = tid & 31;
    int gbase = blockIdx.x * 64;
    int warp_m = wid & 3, warp_n = wid >> 2;
    int M0 = warp_m * 32, N0 = warp_n * 32;

    float acc[2][4][4];
#pragma unroll
    for (int mi = 0; mi < 2; mi++)
#pragma unroll
        for (int ni = 0; ni < 4; ni++)
#pragma unroll
            for (int q = 0; q < 4; q++) acc[mi][ni][q] = 0.f;

    auto issue_stage = [&](int c, int buf) {
        int kc = c * 64;
#pragma unroll
        for (int q = 0; q < 4; q++) {
            int idx = tid + q * 256;
            int m = idx >> 3, seg = idx & 7;
            const __half* src = g_seq_h + (size_t)m * 2048 + kc + seg * 8;
            uint32_t dst = smA + buf * 16384 + SWZ(m * 128 + seg * 16);
            CP_ASYNC16(dst, src);
        }
#pragma unroll
        for (int q = 0; q < 2; q++) {
            int idx = tid + q * 256;
            int n = idx >> 3, seg = idx & 7;
            const __half* src = g_Wih_h + (size_t)(gbase + n) * 2048 + kc + seg * 8;
            uint32_t dst = smB + buf * 8192 + SWZ(n * 128 + seg * 16);
            CP_ASYNC16(dst, src);
        }
    };

    issue_stage(0, 0);
    CP_COMMIT();

    for (int c = 0; c < 32; c++) {
        int buf = c & 1;
        if (c + 1 < 32) issue_stage(c + 1, buf ^ 1);
        CP_COMMIT();
        asm volatile("cp.async.wait_group 1;" ::: "memory");
        __syncthreads();

        uint32_t baseA = smA + buf * 16384;
        uint32_t baseB = smB + buf * 8192;
#pragma unroll
        for (int ks = 0; ks < 4; ks++) {
            uint32_t a[2][4];
#pragma unroll
            for (int mi = 0; mi < 2; mi++) {
                int r = M0 + mi * 16 + (lane & 7) + ((lane >> 3) & 1) * 8;
                int kb = ks * 2 + (lane >> 4);
                uint32_t addr = baseA + SWZ(r * 128 + kb * 16);
                asm volatile(
                    "ldmatrix.sync.aligned.m8n8.x4.shared.b16 {%0,%1,%2,%3}, [%4];"
                    : "=r"(a[mi][0]), "=r"(a[mi][1]), "=r"(a[mi][2]), "=r"(a[mi][3])
                    : "r"(addr));
            }
            uint32_t b[4][2];
#pragma unroll
            for (int ni = 0; ni < 4; ni++) {
                int l2 = lane & 15;
                int n = N0 + ni * 8 + (l2 & 7);
                int kb = ks * 2 + (l2 >> 3);
                uint32_t addr = baseB + SWZ(n * 128 + kb * 16);
                asm volatile(
                    "ldmatrix.sync.aligned.m8n8.x2.shared.b16 {%0,%1}, [%2];"
                    : "=r"(b[ni][0]), "=r"(b[ni][1]) : "r"(addr));
            }
#pragma unroll
            for (int mi = 0; mi < 2; mi++)
#pragma unroll
                for (int ni = 0; ni < 4; ni++) {
                    asm volatile(
                        "mma.sync.aligned.m16n8k16.row.col.f32.f16.f16.f32 "
                        "{%0,%1,%2,%3}, {%4,%5,%6,%7}, {%8,%9}, {%0,%1,%2,%3};"
                        : "+f"(acc[mi][ni][0]), "+f"(acc[mi][ni][1]),
                          "+f"(acc[mi][ni][2]), "+f"(acc[mi][ni][3])
                        : "r"(a[mi][0]), "r"(a[mi][1]), "r"(a[mi][2]), "r"(a[mi][3]),
                          "r"(b[ni][0]), "r"(b[ni][1]));
                }
        }
        __syncthreads();
    }

#pragma unroll
    for (int mi = 0; mi < 2; mi++)
#pragma unroll
        for (int ni = 0; ni < 4; ni++) {
            int g = gbase + N0 + ni * 8 + (lane & 3) * 2;
            float bias0 = b_ih[g] + b_hh[g];
            float bias1 = b_ih[g + 1] + b_hh[g + 1];
#pragma unroll
            for (int half_ = 0; half_ < 2; half_++) {
                int m = M0 + mi * 16 + (lane >> 2) + half_ * 8;
                int tt = m & 31, bb = m >> 5;
                float* outp = g_xproj + (size_t)tt * BB * GATES + (size_t)bb * GATES + g;
                float2 v;
                v.x = acc[mi][ni][half_ * 2 + 0] + bias0;
                v.y = acc[mi][ni][half_ * 2 + 1] + bias1;
                *(float2*)outp = v;
            }
        }
}

// ---------- 5) init h,c ----------
__global__ void init_hc_kernel() {
    int idx = blockIdx.x * 256 + threadIdx.x;  // < 32768
    if (idx < BB * LSTM_H) g_h16[0][idx] = __float2half_rn(0.f);
    else g_c[idx - BB * LSTM_H] = 0.f;
}

// ---------- 6) fused LSTM step: HMMA + per-warp cp.async rings ----------------
// Block (128 thr, 4 warps) owns 8 hidden indices; warp = gate. Each warp
// streams its 8 W_hh rows through a PRIVATE 4-stage x 2KB cp.async ring —
// no block barrier in the hot loop (wait_group + syncwarp only).
// Ring invariant: chunk c lives in stage (c & 3); refill of stage s at
// iteration cc carries chunk cc+4 -> stage (cc+4)&3 == cc&3 == s. Consistent.
// A = 4 fp16 h rows (zero-padded to m16). Grid = 512 blocks.
#define NSTG 4
__global__ void __launch_bounds__(128) lstm_step_mma_kernel(int t) {
    __shared__ __align__(16) __half Bsm[4][NSTG][8 * 128];  // 32 KB
    __shared__ float sgate[4][4][8];  // [gate][batch][jj]
    const __half* __restrict__ hin = g_h16[t & 1];
    __half* __restrict__ hout = g_h16[(t + 1) & 1];
    int tid = threadIdx.x;
    int gate = tid >> 5, lane = tid & 31;
    int l2 = lane & 15;
    int j0 = blockIdx.x * 8;
    uint32_t ring = smem_u32(&Bsm[gate][0][0]);
    const __half* wbase = g_Whh_h + (size_t)(gate * LSTM_H + j0) * LSTM_H;

    // stage layout: row(8) x 256B; swizzle: seg' = (seg ^ row) & 15
    auto load_stage = [&](int s, int cc) {
        int kc = cc * 128;
#pragma unroll
        for (int q = 0; q < 4; q++) {
            int idx = lane + q * 32;
            int row = idx >> 4, seg = idx & 15;
            const __half* src = wbase + (size_t)row * LSTM_H + kc + seg * 8;
            uint32_t dst = ring + s * 2048 + row * 256 + (((seg ^ row) & 15) << 4);
            CP_ASYNC16(dst, src);
        }
        CP_COMMIT();
    };

    // prologue: chunks 0..3 into stages 0..3 (one group each)
#pragma unroll
    for (int s = 0; s < NSTG; s++) load_stage(s, s);

    float c0 = 0.f, c1 = 0.f, c2 = 0.f, c3 = 0.f;
    const uint32_t zero = 0;
    const bool aval = lane < 16;
    const __half* hrow = hin + (lane >> 2) * LSTM_H + (lane & 3) * 2;  // lanes<16

    for (int cc = 0; cc < 32; cc++) {
        // committed = 4 + cc groups; pending<=3 ==> group carrying chunk cc done
        asm volatile("cp.async.wait_group %0;" :: "n"(NSTG - 1) : "memory");
        __syncwarp();
        uint32_t stageBase = ring + (cc & 3) * 2048;
#pragma unroll
        for (int i = 0; i < 8; i++) {
            uint32_t a0 = 0, a2 = 0;
            if (aval) {
                const __half* hq = hrow + cc * 128 + i * 16;
                a0 = *(const uint32_t*)hq;
                a2 = *(const uint32_t*)(hq + 8);
            }
            int kb = i * 2 + (l2 >> 3);
            int row = l2 & 7;
            uint32_t addr = stageBase + row * 256 + (((kb ^ row) & 15) << 4);
            uint32_t b0, b1;
            asm volatile("ldmatrix.sync.aligned.m8n8.x2.shared.b16 {%0,%1}, [%2];"
                         : "=r"(b0), "=r"(b1) : "r"(addr));
            asm volatile(
                "mma.sync.aligned.m16n8k16.row.col.f32.f16.f16.f32 "
                "{%0,%1,%2,%3}, {%4,%5,%6,%7}, {%8,%9}, {%0,%1,%2,%3};"
                : "+f"(c0), "+f"(c1), "+f"(c2), "+f"(c3)
                : "r"(a0), "r"(zero), "r"(a2), "r"(zero), "r"(b0), "r"(b1));
        }
        __syncwarp();  // all lanes done reading this stage before refill
        if (cc + NSTG < 32) load_stage(cc & 3, cc + NSTG);
        else CP_COMMIT();  // empty group keeps wait_group counts aligned
    }

    // lanes 0-15: batch = lane>>2, cols jj = (lane&3)*2, +1
    if (aval) {
        int b = lane >> 2, jj = (lane & 3) * 2;
        sgate[gate][b][jj] = c0;
        sgate[gate][b][jj + 1] = c1;
    }
    __syncthreads();
    if (tid < 32) {
        int b = tid >> 3, jj = tid & 7;
        int j = j0 + jj;
        const float* xp = g_xproj + (size_t)t * BB * GATES + (size_t)b * GATES;
        float gi = sgate[0][b][jj] + xp[j];
        float gf = sgate[1][b][jj] + xp[LSTM_H + j];
        float gg = sgate[2][b][jj] + xp[2 * LSTM_H + j];
        float go = sgate[3][b][jj] + xp[3 * LSTM_H + j];
        float c = g_c[b * LSTM_H + j];
        float si = 1.f / (1.f + expf(-gi));
        float sf = 1.f / (1.f + expf(-gf));
        float so = 1.f / (1.f + expf(-go));
        c = sf * c + si * tanhf(gg);
        g_c[b * LSTM_H + j] = c;
        hout[b * LSTM_H + j] = __float2half_rn(so * tanhf(c));
    }
}

// ---------- 7) final FC ----------
__global__ void final_fc_kernel(const float* __restrict__ fcW,
                                const float* __restrict__ fcb,
                                float* __restrict__ out) {
    int tid = threadIdx.x;  // 128
    int b = tid >> 5, n = tid & 31;
    const __half* hp = g_h16[0] + (size_t)b * LSTM_H + n * 128;  // t=31 -> buf 0
    float s = fcb[0];
#pragma unroll 8
    for (int l = 0; l < 128; l++) s += __half2float(hp[l]) * fcW[l];
    out[tid] = s;
}

extern "C" void kernel_launch(void* const* d_in, const int* in_sizes, int n_in,
                              void* d_out, int out_size) {
    const float* x    = (const float*)d_in[0];
    const int*   ei   = (const int*)d_in[1];
    const float* ln_g = (const float*)d_in[2];
    const float* ln_b = (const float*)d_in[3];
    const float* W1   = (const float*)d_in[4];
    const float* b1   = (const float*)d_in[5];
    const float* W2   = (const float*)d_in[6];
    const float* b2   = (const float*)d_in[7];
    const float* W_ih = (const float*)d_in[8];
    const float* b_ih = (const float*)d_in[9];
    const float* W_hh = (const float*)d_in[10];
    const float* b_hh = (const float*)d_in[11];
    const float* fc_W = (const float*)d_in[12];
    const float* fc_b = (const float*)d_in[13];
    float* out = (float*)d_out;

    build_adj_kernel<<<1, 256>>>(ei);
    gcn_kernel<<<128, 256>>>(x, ln_g, ln_b, W1, b1, W2, b2);
    convert_wih_kernel<<<32768, 256>>>(W_ih);
    xproj_hmma_kernel<<<256, 256>>>(b_ih, b_hh);
    convert_whh_kernel<<<65536, 256>>>(W_hh);
    init_hc_kernel<<<128, 256>>>();
    for (int t = 0; t < TT; t++) {
        lstm_step_mma_kernel<<<512, 128>>>(t);
    }
    final_fc_kernel<<<1, 128>>>(fc_W, fc_b, out);
}

// round 9
// speedup vs baseline: 1.3357x; 1.3357x over previous
#include <cuda_runtime.h>
#include <cuda_fp16.h>
#include <cstdint>

// Problem constants
#define BB 4
#define TT 32
#define NN 32
#define FF 16
#define GH 64
#define LSTM_IN 2048     // NN*GH
#define LSTM_H 4096
#define GATES 16384      // 4*LSTM_H
#define E_EDGES 256

// Scratch (device globals; no dynamic allocation allowed)
__device__ float g_A[NN * NN];
__device__ __align__(16) __half g_seq_h[BB * TT * LSTM_IN];       // 512 KB fp16
__device__ float g_xproj[TT * BB * GATES];                        // 8 MB
__device__ __align__(16) __half g_h16[2][BB * LSTM_H];            // fp16 hidden, dbl-buf
__device__ float g_c[BB * LSTM_H];
__device__ __align__(16) __half g_Whh_h[(size_t)GATES * LSTM_H];  // 128 MiB fp16
__device__ __align__(16) __half g_Wih_h[(size_t)GATES * LSTM_IN]; // 64 MiB fp16

__device__ __forceinline__ uint32_t smem_u32(const void* p) {
    return (uint32_t)__cvta_generic_to_shared(p);
}
#define CP_ASYNC16(dst_u32, src_ptr) \
    asm volatile("cp.async.cg.shared.global [%0], [%1], 16;" :: "r"(dst_u32), "l"(src_ptr))
#define CP_COMMIT() asm volatile("cp.async.commit_group;" ::: "memory")
#define SWZ(x) ((x) ^ (((x) >> 3) & 0x70))

// ---------- 1) adjacency build (handles int32 or int64 edge_index) ----------
__global__ void build_adj_kernel(const int* __restrict__ ei32) {
    __shared__ int is32flag;
    __shared__ int deg[NN];
    __shared__ float dinv[NN];
    __shared__ float As[NN * NN];
    int tid = threadIdx.x;
    if (tid == 0) is32flag = 0;
    for (int i = tid; i < NN; i += blockDim.x) deg[i] = 1;  // self loop
    for (int i = tid; i < NN * NN; i += blockDim.x) As[i] = 0.f;
    __syncthreads();
    int any = 0;
    for (int w = tid * 2 + 1; w < 512; w += blockDim.x * 2) any |= ei32[w];
    if (any) atomicOr(&is32flag, 1);
    __syncthreads();
    const int is32 = is32flag;
    for (int e = tid; e < E_EDGES; e += blockDim.x) {
        int dst = is32 ? ei32[E_EDGES + e] : ei32[2 * (E_EDGES + e)];
        atomicAdd(&deg[dst], 1);
    }
    __syncthreads();
    for (int i = tid; i < NN; i += blockDim.x) dinv[i] = rsqrtf((float)deg[i]);
    __syncthreads();
    for (int e = tid; e < E_EDGES; e += blockDim.x) {
        int src = is32 ? ei32[e] : ei32[2 * e];
        int dst = is32 ? ei32[E_EDGES + e] : ei32[2 * (E_EDGES + e)];
        atomicAdd(&As[dst * NN + src], dinv[src] * dinv[dst]);
    }
    for (int n = tid; n < NN; n += blockDim.x)
        atomicAdd(&As[n * NN + n], dinv[n] * dinv[n]);
    __syncthreads();
    for (int i = tid; i < NN * NN; i += blockDim.x) g_A[i] = As[i];
}

// ---------- 2) LayerNorm + GCN x2 -> seq (fp16) ----------
__global__ void __launch_bounds__(256) gcn_kernel(
    const float* __restrict__ x, const float* __restrict__ ln_g,
    const float* __restrict__ ln_b, const float* __restrict__ W1,
    const float* __restrict__ b1, const float* __restrict__ W2,
    const float* __restrict__ b2) {
    __shared__ float xln[NN * FF];
    __shared__ float bufA[NN * GH];
    __shared__ float bufB[NN * GH];
    __shared__ float As[NN * NN];
    int tid = threadIdx.x;
    int bt = blockIdx.x;  // b*TT + t
    const float* xp = x + (size_t)bt * NN * FF;

    for (int i = tid; i < NN * NN; i += 256) As[i] = g_A[i];
    if (tid < NN) {
        float v[FF];
        float mu = 0.f;
#pragma unroll
        for (int f = 0; f < FF; f++) { v[f] = xp[tid * FF + f]; mu += v[f]; }
        mu *= (1.f / FF);
        float var = 0.f;
#pragma unroll
        for (int f = 0; f < FF; f++) { float d = v[f] - mu; var += d * d; }
        var *= (1.f / FF);
        float r = rsqrtf(var + 1e-5f);
#pragma unroll
        for (int f = 0; f < FF; f++)
            xln[tid * FF + f] = (v[f] - mu) * r * ln_g[f] + ln_b[f];
    }
    __syncthreads();
    for (int o = tid; o < NN * GH; o += 256) {
        int n = o >> 6, g = o & 63;
        float s = 0.f;
#pragma unroll
        for (int f = 0; f < FF; f++) s += xln[n * FF + f] * W1[f * GH + g];
        bufA[o] = s;
    }
    __syncthreads();
    for (int o = tid; o < NN * GH; o += 256) {
        int n = o >> 6, g = o & 63;
        float s = b1[g];
#pragma unroll 8
        for (int sn = 0; sn < NN; sn++) s += As[n * NN + sn] * bufA[sn * GH + g];
        bufB[o] = s;
    }
    __syncthreads();
    for (int o = tid; o < NN * GH; o += 256) {
        int n = o >> 6, g = o & 63;
        float s = 0.f;
#pragma unroll 8
        for (int f = 0; f < GH; f++) s += bufB[n * GH + f] * W2[f * GH + g];
        bufA[o] = s;
    }
    __syncthreads();
    for (int o = tid; o < NN * GH; o += 256) {
        int n = o >> 6, g = o & 63;
        float s = b2[g];
#pragma unroll 8
        for (int sn = 0; sn < NN; sn++) s += As[n * NN + sn] * bufA[sn * GH + g];
        g_seq_h[(size_t)bt * LSTM_IN + o] = __float2half_rn(s);
    }
}

// ---------- 3) converts ----------
__global__ void __launch_bounds__(256) convert_whh_kernel(const float* __restrict__ Whh) {
    size_t i = ((size_t)blockIdx.x * 256 + threadIdx.x) * 4;
    float4 v = *(const float4*)(Whh + i);
    __half2* out = (__half2*)(g_Whh_h + i);
    out[0] = __floats2half2_rn(v.x, v.y);
    out[1] = __floats2half2_rn(v.z, v.w);
}
__global__ void __launch_bounds__(256) convert_wih_kernel(const float* __restrict__ Wih) {
    size_t i = ((size_t)blockIdx.x * 256 + threadIdx.x) * 4;
    float4 v = *(const float4*)(Wih + i);
    __half2* out = (__half2*)(g_Wih_h + i);
    out[0] = __floats2half2_rn(v.x, v.y);
    out[1] = __floats2half2_rn(v.z, v.w);
}

// ---------- 4) x_proj GEMM on tensor cores (HMMA) -----------------------------
__global__ void __launch_bounds__(256) xproj_hmma_kernel(
    const float* __restrict__ b_ih, const float* __restrict__ b_hh) {
    __shared__ __align__(16) char sm[49152];  // A: 2x16KB @0, B: 2x8KB @32768
    const uint32_t smA = smem_u32(sm);
    const uint32_t smB = smA + 32768;
    int tid = threadIdx.x, wid = tid >> 5, lane = tid & 31;
    int gbase = blockIdx.x * 64;
    int warp_m = wid & 3, warp_n = wid >> 2;
    int M0 = warp_m * 32, N0 = warp_n * 32;

    float acc[2][4][4];
#pragma unroll
    for (int mi = 0; mi < 2; mi++)
#pragma unroll
        for (int ni = 0; ni < 4; ni++)
#pragma unroll
            for (int q = 0; q < 4; q++) acc[mi][ni][q] = 0.f;

    auto issue_stage = [&](int c, int buf) {
        int kc = c * 64;
#pragma unroll
        for (int q = 0; q < 4; q++) {
            int idx = tid + q * 256;
            int m = idx >> 3, seg = idx & 7;
            const __half* src = g_seq_h + (size_t)m * 2048 + kc + seg * 8;
            uint32_t dst = smA + buf * 16384 + SWZ(m * 128 + seg * 16);
            CP_ASYNC16(dst, src);
        }
#pragma unroll
        for (int q = 0; q < 2; q++) {
            int idx = tid + q * 256;
            int n = idx >> 3, seg = idx & 7;
            const __half* src = g_Wih_h + (size_t)(gbase + n) * 2048 + kc + seg * 8;
            uint32_t dst = smB + buf * 8192 + SWZ(n * 128 + seg * 16);
            CP_ASYNC16(dst, src);
        }
    };

    issue_stage(0, 0);
    CP_COMMIT();

    for (int c = 0; c < 32; c++) {
        int buf = c & 1;
        if (c + 1 < 32) issue_stage(c + 1, buf ^ 1);
        CP_COMMIT();
        asm volatile("cp.async.wait_group 1;" ::: "memory");
        __syncthreads();

        uint32_t baseA = smA + buf * 16384;
        uint32_t baseB = smB + buf * 8192;
#pragma unroll
        for (int ks = 0; ks < 4; ks++) {
            uint32_t a[2][4];
#pragma unroll
            for (int mi = 0; mi < 2; mi++) {
                int r = M0 + mi * 16 + (lane & 7) + ((lane >> 3) & 1) * 8;
                int kb = ks * 2 + (lane >> 4);
                uint32_t addr = baseA + SWZ(r * 128 + kb * 16);
                asm volatile(
                    "ldmatrix.sync.aligned.m8n8.x4.shared.b16 {%0,%1,%2,%3}, [%4];"
                    : "=r"(a[mi][0]), "=r"(a[mi][1]), "=r"(a[mi][2]), "=r"(a[mi][3])
                    : "r"(addr));
            }
            uint32_t b[4][2];
#pragma unroll
            for (int ni = 0; ni < 4; ni++) {
                int l2 = lane & 15;
                int n = N0 + ni * 8 + (l2 & 7);
                int kb = ks * 2 + (l2 >> 3);
                uint32_t addr = baseB + SWZ(n * 128 + kb * 16);
                asm volatile(
                    "ldmatrix.sync.aligned.m8n8.x2.shared.b16 {%0,%1}, [%2];"
                    : "=r"(b[ni][0]), "=r"(b[ni][1]) : "r"(addr));
            }
#pragma unroll
            for (int mi = 0; mi < 2; mi++)
#pragma unroll
                for (int ni = 0; ni < 4; ni++) {
                    asm volatile(
                        "mma.sync.aligned.m16n8k16.row.col.f32.f16.f16.f32 "
                        "{%0,%1,%2,%3}, {%4,%5,%6,%7}, {%8,%9}, {%0,%1,%2,%3};"
                        : "+f"(acc[mi][ni][0]), "+f"(acc[mi][ni][1]),
                          "+f"(acc[mi][ni][2]), "+f"(acc[mi][ni][3])
                        : "r"(a[mi][0]), "r"(a[mi][1]), "r"(a[mi][2]), "r"(a[mi][3]),
                          "r"(b[ni][0]), "r"(b[ni][1]));
                }
        }
        __syncthreads();
    }

#pragma unroll
    for (int mi = 0; mi < 2; mi++)
#pragma unroll
        for (int ni = 0; ni < 4; ni++) {
            int g = gbase + N0 + ni * 8 + (lane & 3) * 2;
            float bias0 = b_ih[g] + b_hh[g];
            float bias1 = b_ih[g + 1] + b_hh[g + 1];
#pragma unroll
            for (int half_ = 0; half_ < 2; half_++) {
                int m = M0 + mi * 16 + (lane >> 2) + half_ * 8;
                int tt = m & 31, bb = m >> 5;
                float* outp = g_xproj + (size_t)tt * BB * GATES + (size_t)bb * GATES + g;
                float2 v;
                v.x = acc[mi][ni][half_ * 2 + 0] + bias0;
                v.y = acc[mi][ni][half_ * 2 + 1] + bias1;
                *(float2*)outp = v;
            }
        }
}

// ---------- 5) init h,c ----------
__global__ void init_hc_kernel() {
    int idx = blockIdx.x * 256 + threadIdx.x;  // < 32768
    if (idx < BB * LSTM_H) g_h16[0][idx] = __float2half_rn(0.f);
    else g_c[idx - BB * LSTM_H] = 0.f;
}

// ---------- 6) fused LSTM step: HMMA, block-wide 5-stage cp.async pipeline ----
// Round-6 structure (block-wide 8KB stages, one __syncthreads per chunk) with
// one extra stage: NSTG=5, prologue 4 chunks, wait_group 3 -> 4 chunks (32KB)
// in flight per block. Ring: chunk c -> stage c%5; refill target at iter cc is
// (cc+4)%5 == (cc-1)%5, the stage consumed LAST iteration, made safe by this
// iteration's __syncthreads before the refill issue.
// Block 128 thr: warp = gate, 8 j's per block. A = 4 fp16 h rows (padded m16).
#define NSTG 5
__global__ void __launch_bounds__(128) lstm_step_mma_kernel(int t) {
    __shared__ __align__(16) __half Bsm[NSTG * 2 * 32 * 64];  // 40 KB
    __shared__ float sgate[4][4][8];  // [gate][batch][jj]
    const __half* __restrict__ hin = g_h16[t & 1];
    __half* __restrict__ hout = g_h16[(t + 1) & 1];
    int tid = threadIdx.x;
    int gate = tid >> 5, lane = tid & 31;
    int l2 = lane & 15;
    int j0 = blockIdx.x * 8;
    const uint32_t smB = smem_u32(Bsm);

    // stage = [subchunk(64h)][row 32][64 halves], 128B rows, SW128
    auto load_stage = [&](int s, int cc) {
        int kc = cc * 128;
#pragma unroll
        for (int q = 0; q < 4; q++) {
            int idx = tid + q * 128;
            int r = idx >> 4, seg = idx & 15;
            const __half* src = g_Whh_h +
                (size_t)((r >> 3) * LSTM_H + j0 + (r & 7)) * LSTM_H + kc + seg * 8;
            uint32_t dst = smB + s * 8192 + (seg >> 3) * 4096 + SWZ(r * 128 + (seg & 7) * 16);
            CP_ASYNC16(dst, src);
        }
        CP_COMMIT();
    };

    // prologue: chunks 0..3 -> stages 0..3 (4 groups)
    load_stage(0, 0);
    load_stage(1, 1);
    load_stage(2, 2);
    load_stage(3, 3);

    float c0 = 0.f, c1 = 0.f, c2 = 0.f, c3 = 0.f;
    const uint32_t zero = 0;
    const bool aval = lane < 16;
    const __half* hrow = hin + (lane >> 2) * LSTM_H + (lane & 3) * 2;  // lanes<16

    int stage = 0, rstage = 4;
    for (int cc = 0; cc < 32; cc++) {
        // committed before this wait = 4 + cc groups; pending<=3 => chunk cc done
        asm volatile("cp.async.wait_group 3;" ::: "memory");
        __syncthreads();
        if (cc + 4 < 32) load_stage(rstage, cc + 4);
        else CP_COMMIT();  // keep group accounting aligned in the tail
        uint32_t stageBase = smB + stage * 8192;
#pragma unroll
        for (int i = 0; i < 8; i++) {
            uint32_t a0 = 0, a2 = 0;
            if (aval) {
                const __half* hq = hrow + cc * 128 + i * 16;
                a0 = *(const uint32_t*)hq;
                a2 = *(const uint32_t*)(hq + 8);
            }
            uint32_t addr = stageBase + (i >> 2) * 4096 +
                SWZ((gate * 8 + (l2 & 7)) * 128 + (((i & 3) * 2) + (l2 >> 3)) * 16);
            uint32_t b0, b1;
            asm volatile("ldmatrix.sync.aligned.m8n8.x2.shared.b16 {%0,%1}, [%2];"
                         : "=r"(b0), "=r"(b1) : "r"(addr));
            asm volatile(
                "mma.sync.aligned.m16n8k16.row.col.f32.f16.f16.f32 "
                "{%0,%1,%2,%3}, {%4,%5,%6,%7}, {%8,%9}, {%0,%1,%2,%3};"
                : "+f"(c0), "+f"(c1), "+f"(c2), "+f"(c3)
                : "r"(a0), "r"(zero), "r"(a2), "r"(zero), "r"(b0), "r"(b1));
        }
        if (++stage == NSTG) stage = 0;
        if (++rstage == NSTG) rstage = 0;
    }

    // lanes 0-15: batch = lane>>2, cols jj = (lane&3)*2, +1
    if (aval) {
        int b = lane >> 2, jj = (lane & 3) * 2;
        sgate[gate][b][jj] = c0;
        sgate[gate][b][jj + 1] = c1;
    }
    __syncthreads();
    if (tid < 32) {
        int b = tid >> 3, jj = tid & 7;
        int j = j0 + jj;
        const float* xp = g_xproj + (size_t)t * BB * GATES + (size_t)b * GATES;
        float gi = sgate[0][b][jj] + xp[j];
        float gf = sgate[1][b][jj] + xp[LSTM_H + j];
        float gg = sgate[2][b][jj] + xp[2 * LSTM_H + j];
        float go = sgate[3][b][jj] + xp[3 * LSTM_H + j];
        float c = g_c[b * LSTM_H + j];
        float si = 1.f / (1.f + expf(-gi));
        float sf = 1.f / (1.f + expf(-gf));
        float so = 1.f / (1.f + expf(-go));
        c = sf * c + si * tanhf(gg);
        g_c[b * LSTM_H + j] = c;
        hout[b * LSTM_H + j] = __float2half_rn(so * tanhf(c));
    }
}

// ---------- 7) final FC ----------
__global__ void final_fc_kernel(const float* __restrict__ fcW,
                                const float* __restrict__ fcb,
                                float* __restrict__ out) {
    int tid = threadIdx.x;  // 128
    int b = tid >> 5, n = tid & 31;
    const __half* hp = g_h16[0] + (size_t)b * LSTM_H + n * 128;  // t=31 -> buf 0
    float s = fcb[0];
#pragma unroll 8
    for (int l = 0; l < 128; l++) s += __half2float(hp[l]) * fcW[l];
    out[tid] = s;
}

extern "C" void kernel_launch(void* const* d_in, const int* in_sizes, int n_in,
                              void* d_out, int out_size) {
    const float* x    = (const float*)d_in[0];
    const int*   ei   = (const int*)d_in[1];
    const float* ln_g = (const float*)d_in[2];
    const float* ln_b = (const float*)d_in[3];
    const float* W1   = (const float*)d_in[4];
    const float* b1   = (const float*)d_in[5];
    const float* W2   = (const float*)d_in[6];
    const float* b2   = (const float*)d_in[7];
    const float* W_ih = (const float*)d_in[8];
    const float* b_ih = (const float*)d_in[9];
    const float* W_hh = (const float*)d_in[10];
    const float* b_hh = (const float*)d_in[11];
    const float* fc_W = (const float*)d_in[12];
    const float* fc_b = (const float*)d_in[13];
    float* out = (float*)d_out;

    build_adj_kernel<<<1, 256>>>(ei);
    gcn_kernel<<<128, 256>>>(x, ln_g, ln_b, W1, b1, W2, b2);
    convert_wih_kernel<<<32768, 256>>>(W_ih);
    xproj_hmma_kernel<<<256, 256>>>(b_ih, b_hh);
    convert_whh_kernel<<<65536, 256>>>(W_hh);
    init_hc_kernel<<<128, 256>>>();
    for (int t = 0; t < TT; t++) {
        lstm_step_mma_kernel<<<512, 128>>>(t);
    }
    final_fc_kernel<<<1, 128>>>(fc_W, fc_b, out);
}